// round 15
// baseline (speedup 1.0000x reference)
#include <cuda_runtime.h>
#include <cuda_fp16.h>
#include <cstdint>

typedef __half h16;
#define NK   10000
#define NE   100000
#define D    128
#define DD   (128*128)
#define EDG  1600000

// ---------------- scratch (static __device__ — no allocations allowed) ----------------
__device__ __align__(16) h16 g_ee[NE*D];
__device__ __align__(16) h16 g_ii[NK*D];
__device__ __align__(16) h16 g_ke[NK*D];
__device__ __align__(16) h16 g_ii2[NK*D];
__device__ __align__(16) h16 g_nb[NE*D];
__device__ __align__(16) h16 g_nc[NE*D];
__device__ __align__(16) h16 g_hiI[NE*D];
__device__ __align__(16) h16 g_sc[NE*D];
__device__ __align__(16) h16 g_W[7][128*256];       // per stage [128 n][256 k]
__device__ __align__(16) float g_M1[DD], g_M2[DD], g_M3[DD], g_M4[DD];
__device__ __align__(16) float g_c1[D], g_c2[D];
// CSR (B = belong, C = collab) — deg/pub are zero at entry (load-time init + tail re-zero)
__device__ __align__(16) int   g_degB[NE], g_degC[NE];
__device__ __align__(16) int   g_rpB[NE+1], g_rpC[NE+1];
__device__ __align__(16) int   g_curB[NE], g_curC[NE];
__device__ __align__(16) int   g_esrcB[EDG], g_esrcC[EDG];
__device__ __align__(16) float g_ewC[EDG];
__device__ __align__(16) unsigned long long g_pub[2*128];   // packed (sum<<32)|flag

// ---------------- host-side aux (streams/events created once) ----------------
struct Aux {
    cudaStream_t s2, s3, s4;
    cudaEvent_t evF, evJ2, evJ3, evJ4, evAB, evT;
    Aux() {
        cudaStreamCreateWithFlags(&s2, cudaStreamNonBlocking);
        cudaStreamCreateWithFlags(&s3, cudaStreamNonBlocking);
        cudaStreamCreateWithFlags(&s4, cudaStreamNonBlocking);
        cudaEventCreateWithFlags(&evF,  cudaEventDisableTiming);
        cudaEventCreateWithFlags(&evJ2, cudaEventDisableTiming);
        cudaEventCreateWithFlags(&evJ3, cudaEventDisableTiming);
        cudaEventCreateWithFlags(&evJ4, cudaEventDisableTiming);
        cudaEventCreateWithFlags(&evAB, cudaEventDisableTiming);
        cudaEventCreateWithFlags(&evT,  cudaEventDisableTiming);
    }
};
static Aux g_aux;

// ---------------- small helpers ----------------
__device__ __forceinline__ uint32_t s2u(const void* p) {
    uint32_t a;
    asm("{ .reg .u64 t; cvta.to.shared.u64 t, %1; cvt.u32.u64 %0, t; }" : "=r"(a) : "l"(p));
    return a;
}
__device__ __forceinline__ uint32_t packh(h16 a, h16 b) {
    return ((uint32_t)__half_as_ushort(b) << 16) | (uint32_t)__half_as_ushort(a);
}
__device__ __forceinline__ float hlo(uint32_t u) {
    return __half2float(__ushort_as_half((unsigned short)(u & 0xFFFF)));
}
__device__ __forceinline__ float hhi(uint32_t u) {
    return __half2float(__ushort_as_half((unsigned short)(u >> 16)));
}
__device__ __forceinline__ void ldmx4(uint32_t* r, uint32_t addr) {
    asm volatile("ldmatrix.sync.aligned.m8n8.x4.shared.b16 {%0,%1,%2,%3}, [%4];"
                 : "=r"(r[0]), "=r"(r[1]), "=r"(r[2]), "=r"(r[3]) : "r"(addr));
}
__device__ __forceinline__ void mma16816(float* c, const uint32_t* a, uint32_t b0, uint32_t b1) {
    asm volatile("mma.sync.aligned.m16n8k16.row.col.f32.f16.f16.f32 "
                 "{%0,%1,%2,%3}, {%4,%5,%6,%7}, {%8,%9}, {%0,%1,%2,%3};"
                 : "+f"(c[0]), "+f"(c[1]), "+f"(c[2]), "+f"(c[3])
                 : "r"(a[0]), "r"(a[1]), "r"(a[2]), "r"(a[3]), "r"(b0), "r"(b1));
}
__device__ __forceinline__ void cp16(uint32_t s, const void* g) {
    asm volatile("cp.async.cg.shared.global [%0], [%1], 16;" :: "r"(s), "l"(g));
}

// ---------------- SMEM layout ----------------
#define T_ROW    144
#define CH_B     18432
#define CH_BUF   36864
#define TILE_OFF 73728
#define TT_ROW   272
#define SM_TOTAL 108544
#define CF_ROW   528

// ---------------- generic GEMM pass (identical to R14) ----------------
template <int A1S, int A2S, int ACT, int OUT>
__device__ __forceinline__ void gpass(
    char* smem, uint32_t sb, int tid, int lane, int wid, int mbrow, int M,
    const h16* gA1, const h16* gA2, const h16* w, const float* bias,
    h16* go16, float* go32)
{
    int wr = wid & 3, wc = wid >> 2;

    auto load_chunk = [&](int c, int buf) {
        int k0 = (c & 1) * 64;
        bool a_smem = (c < 2) ? (A1S != 0) : (A2S != 0);
        const h16* A = (c < 2) ? gA1 : gA2;
        if (!a_smem) {
#pragma unroll
            for (int u = 0; u < 4; ++u) {
                int i = u * 256 + tid;
                int row = i >> 3, g = i & 7;
                int grow = mbrow + row;
                if (grow < M)
                    cp16(sb + buf * CH_BUF + row * T_ROW + g * 16,
                         A + (size_t)grow * 128 + k0 + g * 8);
            }
        }
#pragma unroll
        for (int u = 0; u < 4; ++u) {
            int i = u * 256 + tid;
            int n = i >> 3, g = i & 7;
            cp16(sb + buf * CH_BUF + CH_B + n * T_ROW + g * 16,
                 w + n * 256 + c * 64 + g * 8);
        }
        asm volatile("cp.async.commit_group;" ::: "memory");
    };

    load_chunk(0, 0);
    load_chunk(1, 1);

    float acc[2][8][4];
#pragma unroll
    for (int mi = 0; mi < 2; ++mi)
#pragma unroll
        for (int ni = 0; ni < 8; ++ni)
#pragma unroll
            for (int q = 0; q < 4; ++q) acc[mi][ni][q] = 0.f;

    int l15 = lane & 15, lkb = (lane >> 4) * 16;

#pragma unroll
    for (int c = 0; c < 4; ++c) {
        if (c < 3) asm volatile("cp.async.wait_group 1;" ::: "memory");
        else       asm volatile("cp.async.wait_group 0;" ::: "memory");
        __syncthreads();

        int buf = c & 1;
        bool a_smem = (c < 2) ? (A1S != 0) : (A2S != 0);
        uint32_t Ab;
        int arow;
        if (a_smem) {
            Ab = sb + TILE_OFF + (uint32_t)(wr * 32 + l15) * TT_ROW + lkb + (c & 1) * 128;
            arow = TT_ROW;
        } else {
            Ab = sb + buf * CH_BUF + (uint32_t)(wr * 32 + l15) * T_ROW + lkb;
            arow = T_ROW;
        }
        uint32_t Bb = sb + buf * CH_BUF + CH_B + (uint32_t)(wc * 64 + l15) * T_ROW + lkb;
#pragma unroll
        for (int s = 0; s < 4; ++s) {
            uint32_t Aks = Ab + s * 32;
            uint32_t Bks = Bb + s * 32;
            uint32_t A0[4], A1[4];
            ldmx4(A0, Aks);
            ldmx4(A1, Aks + 16 * arow);
            uint32_t B[4][4];
#pragma unroll
            for (int nb = 0; nb < 4; ++nb) ldmx4(B[nb], Bks + nb * (16 * T_ROW));
#pragma unroll
            for (int ni = 0; ni < 8; ++ni) {
                int nb = ni >> 1, hb = ni & 1;
                mma16816(acc[0][ni], A0, B[nb][hb], B[nb][2 + hb]);
                mma16816(acc[1][ni], A1, B[nb][hb], B[nb][2 + hb]);
            }
        }
        __syncthreads();
        if (c + 2 < 4) load_chunk(c + 2, buf);
    }

    int quad = lane >> 2, tq = lane & 3;
    if (OUT == 2) {
#pragma unroll
        for (int ni = 0; ni < 8; ++ni) {
            int cbase = wc * 64 + ni * 8 + tq * 2;
            float bv0 = __ldg(bias + cbase), bv1 = __ldg(bias + cbase + 1);
#pragma unroll
            for (int mi = 0; mi < 2; ++mi)
#pragma unroll
                for (int h = 0; h < 2; ++h) {
                    int row = wr * 32 + mi * 16 + quad + h * 8;
                    float x0 = acc[mi][ni][2 * h + 0] + bv0;
                    float x1 = acc[mi][ni][2 * h + 1] + bv1;
                    if (ACT == 1) { x0 = fmaxf(x0, 0.f); x1 = fmaxf(x1, 0.f); }
                    if (ACT == 2) { x0 = (x0 >= 0.f) ? x0 : 0.2f * x0;
                                    x1 = (x1 >= 0.f) ? x1 : 0.2f * x1; }
                    *(float2*)(smem + row * CF_ROW + cbase * 4) = make_float2(x0, x1);
                }
        }
        __syncthreads();
#pragma unroll
        for (int it = 0; it < 16; ++it) {
            int r = wid * 16 + it;
            int grow = mbrow + r;
            if (grow >= M) continue;
            float4 v = *(float4*)(smem + r * CF_ROW + lane * 16);
            *(float4*)(go32 + (size_t)grow * 128 + lane * 4) = v;
        }
    } else {
#pragma unroll
        for (int ni = 0; ni < 8; ++ni) {
            int cbase = wc * 64 + ni * 8 + tq * 2;
            float bv0 = __ldg(bias + cbase), bv1 = __ldg(bias + cbase + 1);
#pragma unroll
            for (int mi = 0; mi < 2; ++mi)
#pragma unroll
                for (int h = 0; h < 2; ++h) {
                    int row = wr * 32 + mi * 16 + quad + h * 8;
                    float x0 = acc[mi][ni][2 * h + 0] + bv0;
                    float x1 = acc[mi][ni][2 * h + 1] + bv1;
                    if (ACT == 1) { x0 = fmaxf(x0, 0.f); x1 = fmaxf(x1, 0.f); }
                    if (ACT == 2) { x0 = (x0 >= 0.f) ? x0 : 0.2f * x0;
                                    x1 = (x1 >= 0.f) ? x1 : 0.2f * x1; }
                    *(uint32_t*)(smem + TILE_OFF + row * TT_ROW + cbase * 2) =
                        packh(__float2half_rn(x0), __float2half_rn(x1));
                }
        }
        __syncthreads();
        if (OUT == 1) {
            int row2 = lane >> 4, colg = lane & 15;
#pragma unroll
            for (int it = 0; it < 8; ++it) {
                int r = wid * 16 + it * 2 + row2;
                int grow = mbrow + r;
                if (grow >= M) continue;
                uint4 v = *(uint4*)(smem + TILE_OFF + r * TT_ROW + colg * 16);
                *(uint4*)(go16 + (size_t)grow * 128 + colg * 8) = v;
            }
        }
    }
}

// ---------------- GEMM kernels ----------------
__global__ void __launch_bounds__(256, 2) gemm1(
    const h16* __restrict__ a1, const h16* __restrict__ a2,
    const h16* __restrict__ w, const float* __restrict__ bias,
    h16* __restrict__ o, int M)
{
    extern __shared__ char smem[];
    uint32_t sb = s2u(smem);
    gpass<0, 0, 0, 1>(smem, sb, threadIdx.x, threadIdx.x & 31, threadIdx.x >> 5,
                      blockIdx.x * 128, M, a1, a2, w, bias, o, nullptr);
}

__global__ void __launch_bounds__(256, 2) fused3_a(
    const h16* __restrict__ ee, const h16* __restrict__ nb,
    const h16* __restrict__ w0, const float* __restrict__ b0,
    const h16* __restrict__ w1, const float* __restrict__ b1,
    const h16* __restrict__ w2, const float* __restrict__ b2,
    h16* __restrict__ hiI, h16* __restrict__ sc, int M)
{
    extern __shared__ char smem[];
    uint32_t sb = s2u(smem);
    int tid = threadIdx.x, lane = tid & 31, wid = tid >> 5, mb = blockIdx.x * 128;
    gpass<0, 0, 1, 0>(smem, sb, tid, lane, wid, mb, M, ee, nb, w0, b0, nullptr, nullptr);
    gpass<1, 0, 0, 1>(smem, sb, tid, lane, wid, mb, M, nullptr, nb, w1, b1, hiI, nullptr);
    gpass<1, 0, 0, 1>(smem, sb, tid, lane, wid, mb, M, nullptr, ee, w2, b2, sc, nullptr);
}

__global__ void __launch_bounds__(256, 2) fused3_b(
    const h16* __restrict__ ee, const h16* __restrict__ nc,
    const h16* __restrict__ w0, const float* __restrict__ b0,
    const h16* __restrict__ w1, const float* __restrict__ b1,
    const h16* __restrict__ hiI, const h16* __restrict__ w2,
    const float* __restrict__ b2, float* __restrict__ out, int M)
{
    extern __shared__ char smem[];
    uint32_t sb = s2u(smem);
    int tid = threadIdx.x, lane = tid & 31, wid = tid >> 5, mb = blockIdx.x * 128;
    gpass<0, 0, 1, 0>(smem, sb, tid, lane, wid, mb, M, ee, nc, w0, b0, nullptr, nullptr);
    gpass<1, 0, 0, 0>(smem, sb, tid, lane, wid, mb, M, nullptr, nc, w1, b1, nullptr, nullptr);
    gpass<0, 1, 2, 2>(smem, sb, tid, lane, wid, mb, M, hiI, nullptr, w2, b2, nullptr, out);
}

// ---------------- weight split helper ----------------
__device__ __forceinline__ void conv_w_one(int stage, int idx, const float* a, const float* b) {
    int n = idx >> 8, k = idx & 255;
    float v = b ? (k < 128 ? a[n * 128 + k] : b[n * 128 + (k - 128)]) : a[idx];
    g_W[stage][idx] = __float2half_rn(v);
}

// ---------------- prep0 ----------------
__global__ void prep0(const float* __restrict__ ii, const float* __restrict__ k_emb,
                      const float* __restrict__ w4W) {
    int bid = blockIdx.x, tid = threadIdx.x;
    if (bid < 5000) {
        int i = bid * 256 + tid;
        g_ii[i] = __float2half_rn(ii[i]);
    } else if (bid < 10000) {
        int i = (bid - 5000) * 256 + tid;
        g_ke[i] = __float2half_rn(k_emb[i]);
    } else {
        int idx = (bid - 10000) * 256 + tid;
        g_W[0][idx] = __float2half_rn(w4W[idx]);
    }
}

// ---------------- prepE1 / prepE2 ----------------
__global__ void prepE1(const float* __restrict__ e_emb,
                       const float* __restrict__ w2W, const float* __restrict__ w2b,
                       const float* __restrict__ w3W, const float* __restrict__ w3b,
                       const float* __restrict__ ekS1, const float* __restrict__ ekN1,
                       const float* __restrict__ eeS1, const float* __restrict__ eeN1,
                       const float* __restrict__ ekb1, const float* __restrict__ eeb1,
                       const float* __restrict__ ek_self, const float* __restrict__ ek_neigh,
                       const float* __restrict__ w1W, const float* __restrict__ ee_self,
                       const float* __restrict__ ee_neigh, const float* __restrict__ combW) {
    int bid = blockIdx.x, tid = threadIdx.x;
    if (bid < 50000) {
        int i = bid * 256 + tid;
        g_ee[i] = __float2half_rn(e_emb[i]);
    } else if (bid < 50256) {
        int lb = bid - 50000;
        int mat = lb >> 6;
        int idx = (lb & 63) * 256 + tid;
        const float* A = (mat < 2) ? w2W : w3W;
        const float* B = (mat == 0) ? ekS1 : (mat == 1) ? ekN1 : (mat == 2) ? eeS1 : eeN1;
        float* O = (mat == 0) ? g_M1 : (mat == 1) ? g_M2 : (mat == 2) ? g_M3 : g_M4;
        int n = idx >> 7, k = idx & 127;
        float acc = 0.f;
#pragma unroll 8
        for (int j = 0; j < 128; ++j)
            acc += A[n * 128 + j] * B[j * 128 + k];
        O[idx] = acc;
    } else if (bid == 50256) {
        int t = tid;
        if (t < 128) {
            float a = 0.f, b = 0.f;
#pragma unroll 8
            for (int j = 0; j < 128; ++j) {
                a += w2W[t * 128 + j] * ekb1[j];
                b += w3W[t * 128 + j] * eeb1[j];
            }
            g_c1[t] = a + w2b[t];
            g_c2[t] = b + w3b[t];
        }
    } else {
        int lb = bid - 50257;
        int which = lb >> 7;
        int idx = (lb & 127) * 256 + tid;
        if (which == 0)      conv_w_one(1, idx, ek_self, ek_neigh);
        else if (which == 1) conv_w_one(3, idx, w1W, nullptr);
        else if (which == 2) conv_w_one(4, idx, ee_self, ee_neigh);
        else                 conv_w_one(6, idx, combW, nullptr);
    }
}

__global__ void prepE2() {
    int bid = blockIdx.x;
    int idx = (bid & 127) * 256 + threadIdx.x;
    if (bid < 128) conv_w_one(2, idx, g_M1, g_M2);
    else           conv_w_one(5, idx, g_M3, g_M4);
}

// ---------------- CSR build (deg/pub are zero at entry; re-zeroed at tail) ----------------
__global__ void count2_k(const int* __restrict__ dst, int* __restrict__ deg, int E) {
    int h = (E + 1) >> 1;
    int i = blockIdx.x * blockDim.x + threadIdx.x;
    if (i >= h) return;
    int j = i + h;
    int d0 = dst[i];
    if (j < E) {
        int d1 = dst[j];
        atomicAdd(&deg[d0], 1);
        atomicAdd(&deg[d1], 1);
    } else {
        atomicAdd(&deg[d0], 1);
    }
}
// single-kernel exclusive scan with decoupled lookback (all blocks resident: 98 <= 148)
__global__ void scan_lb(const int* __restrict__ deg, int* __restrict__ rp,
                        int* __restrict__ cur, unsigned long long* __restrict__ pub,
                        int nblk) {
    __shared__ int ws[32];
    __shared__ int s_pref;
    int bid = blockIdx.x, tid = threadIdx.x, lane = tid & 31, wid = tid >> 5;
    int i = bid * 1024 + tid;
    int v = (i < NE) ? deg[i] : 0;
    int inc = v;
#pragma unroll
    for (int o = 1; o < 32; o <<= 1) {
        int x = __shfl_up_sync(0xFFFFFFFFu, inc, o);
        if (lane >= o) inc += x;
    }
    if (lane == 31) ws[wid] = inc;
    __syncthreads();
    if (wid == 0) {
        int s = ws[lane];
#pragma unroll
        for (int o = 1; o < 32; o <<= 1) {
            int x = __shfl_up_sync(0xFFFFFFFFu, s, o);
            if (lane >= o) s += x;
        }
        ws[lane] = s;
    }
    __syncthreads();
    int off = wid ? ws[wid - 1] : 0;
    int total = ws[31];
    __syncthreads();
    if (tid == 0)
        atomicExch(&pub[bid], ((unsigned long long)(unsigned)total << 32) | 1ull);
    int contrib = 0;
    if (tid < bid) {
        unsigned long long x;
        do { x = atomicAdd(&pub[tid], 0ull); } while (!(x & 1ull));
        contrib = (int)(x >> 32);
    }
#pragma unroll
    for (int o = 16; o > 0; o >>= 1)
        contrib += __shfl_xor_sync(0xFFFFFFFFu, contrib, o);
    if (lane == 0) ws[wid] = contrib;
    __syncthreads();
    if (tid == 0) {
        int s = 0;
        for (int w = 0; w < 32; ++w) s += ws[w];
        s_pref = s;
    }
    __syncthreads();
    int base = s_pref;
    if (i < NE) {
        int val = base + off + inc - v;
        rp[i] = val;
        cur[i] = val;
    }
    if (bid == nblk - 1 && tid == 0) rp[NE] = base + total;
}
template <int WEIGHTED>
__global__ void scatter2_k(const int* __restrict__ src, const int* __restrict__ dst,
                           const float* __restrict__ ewin, int* __restrict__ cur,
                           int* __restrict__ esrc, float* __restrict__ ewout, int E) {
    int h = (E + 1) >> 1;
    int i = blockIdx.x * blockDim.x + threadIdx.x;
    if (i >= h) return;
    int j = i + h;
    bool has2 = j < E;
    int d0 = dst[i];
    int d1 = has2 ? dst[j] : 0;
    int p0 = atomicAdd(&cur[d0], 1);
    int p1 = has2 ? atomicAdd(&cur[d1], 1) : 0;
    esrc[p0] = src[i];
    if (has2) esrc[p1] = src[j];
    if (WEIGHTED) {
        ewout[p0] = ewin[i];
        if (has2) ewout[p1] = ewin[j];
    }
}
// tail: restore deg/pub invariants for both graphs (hidden under aggC/F2)
__global__ void tail_zero() {
    int i = blockIdx.x * blockDim.x + threadIdx.x;
    if (i < NE) { g_degB[i] = 0; g_degC[i] = 0; }
    if (blockIdx.x == 0 && threadIdx.x < 256) g_pub[threadIdx.x] = 0ull;
}

// ---------------- mean aggregation: warp per dst node, 2 edges/iter, uint4 loads ----------------
template <int WEIGHTED>
__global__ void aggregate_kernel(const h16* __restrict__ sh, h16* __restrict__ oh,
                                 const int* __restrict__ rowptr, const int* __restrict__ esrc,
                                 const float* __restrict__ ew, int n) {
    int gw = (blockIdx.x * blockDim.x + threadIdx.x) >> 5;
    int lane = threadIdx.x & 31;
    if (gw >= n) return;
    int s0 = rowptr[gw], s1 = rowptr[gw + 1];
    int half = lane >> 4, l16 = lane & 15;
    float a[8];
#pragma unroll
    for (int d = 0; d < 8; ++d) a[d] = 0.f;
    int j = s0;
    for (; j + 1 < s1; j += 2) {
        int e = j + half;
        int sidx = esrc[e];
        uint4 u = *(const uint4*)(sh + (size_t)sidx * D + l16 * 8);
        float w = WEIGHTED ? ew[e] : 1.0f;
        a[0] += hlo(u.x) * w; a[1] += hhi(u.x) * w;
        a[2] += hlo(u.y) * w; a[3] += hhi(u.y) * w;
        a[4] += hlo(u.z) * w; a[5] += hhi(u.z) * w;
        a[6] += hlo(u.w) * w; a[7] += hhi(u.w) * w;
    }
    if (j < s1 && half == 0) {
        int sidx = esrc[j];
        uint4 u = *(const uint4*)(sh + (size_t)sidx * D + l16 * 8);
        float w = WEIGHTED ? ew[j] : 1.0f;
        a[0] += hlo(u.x) * w; a[1] += hhi(u.x) * w;
        a[2] += hlo(u.y) * w; a[3] += hhi(u.y) * w;
        a[4] += hlo(u.z) * w; a[5] += hhi(u.z) * w;
        a[6] += hlo(u.w) * w; a[7] += hhi(u.w) * w;
    }
#pragma unroll
    for (int d = 0; d < 8; ++d) a[d] += __shfl_xor_sync(0xFFFFFFFFu, a[d], 16);
    if (half == 0) {
        float inv = 1.0f / fmaxf((float)(s1 - s0), 1.0f);
        uint4 o;
        o.x = packh(__float2half_rn(a[0] * inv), __float2half_rn(a[1] * inv));
        o.y = packh(__float2half_rn(a[2] * inv), __float2half_rn(a[3] * inv));
        o.z = packh(__float2half_rn(a[4] * inv), __float2half_rn(a[5] * inv));
        o.w = packh(__float2half_rn(a[6] * inv), __float2half_rn(a[7] * inv));
        *(uint4*)(oh + (size_t)gw * D + l16 * 8) = o;
    }
}

// ---------------- launch ----------------
extern "C" void kernel_launch(void* const* d_in, const int* in_sizes, int n_in,
                              void* d_out, int out_size) {
    const float* ii      = (const float*)d_in[0];
    const float* e_emb   = (const float*)d_in[1];
    const float* k_emb   = (const float*)d_in[2];
    const float* cf_ew   = (const float*)d_in[3];
    const int*   b_src   = (const int*)d_in[4];
    const int*   b_dst   = (const int*)d_in[5];
    const int*   c_src   = (const int*)d_in[6];
    const int*   c_dst   = (const int*)d_in[7];
    const float* ek_self = (const float*)d_in[8];
    const float* ek_neigh= (const float*)d_in[9];
    const float* ek_bias = (const float*)d_in[10];
    const float* ee_self = (const float*)d_in[11];
    const float* ee_neigh= (const float*)d_in[12];
    const float* ee_bias = (const float*)d_in[13];
    const float* w1W = (const float*)d_in[14];
    const float* w1b = (const float*)d_in[15];
    const float* w2W = (const float*)d_in[16];
    const float* w2b = (const float*)d_in[17];
    const float* w3W = (const float*)d_in[18];
    const float* w3b = (const float*)d_in[19];
    const float* w4W = (const float*)d_in[20];
    const float* w4b = (const float*)d_in[21];
    const float* combW = (const float*)d_in[22];
    const float* combb = (const float*)d_in[23];
    float* out = (float*)d_out;

    int n_k = in_sizes[0] / D;
    int n_e = in_sizes[1] / D;
    int E   = in_sizes[4];

    h16 *ee, *iip, *ke, *ii2, *nb, *nc, *hiI, *sc, *W;
    float *p_c1, *p_c2, *p_ewC;
    int *p_rpB, *p_rpC, *p_esB, *p_esC, *p_degB, *p_degC, *p_curB, *p_curC;
    unsigned long long* p_pub;
    cudaGetSymbolAddress((void**)&ee,  g_ee);
    cudaGetSymbolAddress((void**)&iip, g_ii);
    cudaGetSymbolAddress((void**)&ke,  g_ke);
    cudaGetSymbolAddress((void**)&ii2, g_ii2);
    cudaGetSymbolAddress((void**)&nb,  g_nb);
    cudaGetSymbolAddress((void**)&nc,  g_nc);
    cudaGetSymbolAddress((void**)&hiI, g_hiI);
    cudaGetSymbolAddress((void**)&sc,  g_sc);
    cudaGetSymbolAddress((void**)&W,   g_W);
    cudaGetSymbolAddress((void**)&p_c1, g_c1);   cudaGetSymbolAddress((void**)&p_c2, g_c2);
    cudaGetSymbolAddress((void**)&p_rpB, g_rpB); cudaGetSymbolAddress((void**)&p_rpC, g_rpC);
    cudaGetSymbolAddress((void**)&p_esB, g_esrcB); cudaGetSymbolAddress((void**)&p_esC, g_esrcC);
    cudaGetSymbolAddress((void**)&p_ewC, g_ewC);
    cudaGetSymbolAddress((void**)&p_degB, g_degB); cudaGetSymbolAddress((void**)&p_degC, g_degC);
    cudaGetSymbolAddress((void**)&p_curB, g_curB); cudaGetSymbolAddress((void**)&p_curC, g_curC);
    cudaGetSymbolAddress((void**)&p_pub, g_pub);

    cudaFuncSetAttribute(gemm1,    cudaFuncAttributeMaxDynamicSharedMemorySize, SM_TOTAL);
    cudaFuncSetAttribute(fused3_a, cudaFuncAttributeMaxDynamicSharedMemorySize, SM_TOTAL);
    cudaFuncSetAttribute(fused3_b, cudaFuncAttributeMaxDynamicSharedMemorySize, SM_TOTAL);

    int hE   = (E + 1) / 2;
    int gE2  = (hE + 255) / 256;
    int gNe  = (n_e + 255) / 256;
    int gSc  = (n_e + 1023) / 1024;              // 98 blocks (<= 148 SMs, lookback-safe)
    int gAgg = (n_e * 32 + 255) / 256;
    int gbK  = (n_k + 127) / 128;
    int gbE  = (n_e + 127) / 128;

    // ---- fork ----
    cudaEventRecord(g_aux.evF, 0);
    cudaStreamWaitEvent(g_aux.s2, g_aux.evF, 0);
    cudaStreamWaitEvent(g_aux.s4, g_aux.evF, 0);

    // s2: belong CSR ONLY (no zero — deg/pub are zero at entry)
    count2_k<<<gE2, 256, 0, g_aux.s2>>>(b_dst, p_degB, E);
    scan_lb<<<gSc, 1024, 0, g_aux.s2>>>(p_degB, p_rpB, p_curB, p_pub, gSc);
    scatter2_k<0><<<gE2, 256, 0, g_aux.s2>>>(b_src, b_dst, nullptr, p_curB, p_esB, nullptr, E);
    cudaEventRecord(g_aux.evJ2, g_aux.s2);

    // s4: heavy prep (needed by F1)
    prepE1<<<50769, 256, 0, g_aux.s4>>>(e_emb, w2W, w2b, w3W, w3b,
                                        ek_self + DD, ek_neigh + DD, ee_self + DD, ee_neigh + DD,
                                        ek_bias + D, ee_bias + D,
                                        ek_self, ek_neigh, w1W, ee_self, ee_neigh, combW);
    prepE2<<<256, 256, 0, g_aux.s4>>>();
    cudaEventRecord(g_aux.evJ4, g_aux.s4);

    // main: minimal prep + stage0 GEMM
    prep0<<<10128, 256>>>(ii, k_emb, w4W);
    gemm1<<<gbK, 256, SM_TOTAL>>>(iip, ke, W + 0*32768, w4b, ii2, n_k);

    // join belong CSR → aggB (record event so CSR-C can start right after)
    cudaStreamWaitEvent(0, g_aux.evJ2, 0);
    aggregate_kernel<0><<<gAgg, 256>>>(ii2, nb, p_rpB, p_esB, nullptr, n_e);
    cudaEventRecord(g_aux.evAB, 0);

    // s3: collab CSR — runs concurrently with F1 (compute-bound window)
    cudaStreamWaitEvent(g_aux.s3, g_aux.evAB, 0);
    count2_k<<<gE2, 256, 0, g_aux.s3>>>(c_dst, p_degC, E);
    scan_lb<<<gSc, 1024, 0, g_aux.s3>>>(p_degC, p_rpC, p_curC, p_pub + 128, gSc);
    scatter2_k<1><<<gE2, 256, 0, g_aux.s3>>>(c_src, c_dst, cf_ew, p_curC, p_esC, p_ewC, E);
    cudaEventRecord(g_aux.evJ3, g_aux.s3);

    // main: F1 (overlaps CSR-C)
    cudaStreamWaitEvent(0, g_aux.evJ4, 0);
    fused3_a<<<gbE, 256, SM_TOTAL>>>(ee, nb, W + 1*32768, ek_bias,
                                     W + 2*32768, p_c1, W + 3*32768, w1b,
                                     hiI, sc, n_e);

    // s4: tail re-zero of deg/pub for next replay (hidden under aggC/F2)
    cudaStreamWaitEvent(g_aux.s4, g_aux.evJ3, 0);
    tail_zero<<<gNe, 256, 0, g_aux.s4>>>();
    cudaEventRecord(g_aux.evT, g_aux.s4);

    // join collab CSR → aggC → F2
    cudaStreamWaitEvent(0, g_aux.evJ3, 0);
    aggregate_kernel<1><<<gAgg, 256>>>(sc, nc, p_rpC, p_esC, p_ewC, n_e);
    fused3_b<<<gbE, 256, SM_TOTAL>>>(ee, nc, W + 4*32768, ee_bias,
                                     W + 5*32768, p_c2, hiI, W + 6*32768,
                                     combb, out, n_e);
    // join tail zero into main so capture is fully joined (completes long before F2)
    cudaStreamWaitEvent(0, g_aux.evT, 0);
}

// round 16
// speedup vs baseline: 1.0863x; 1.0863x over previous
#include <cuda_runtime.h>
#include <cuda_fp16.h>
#include <cstdint>

typedef __half h16;
#define NK   10000
#define NE   100000
#define D    128
#define DD   (128*128)
#define EDG  1600000

// ---------------- scratch (static __device__ — no allocations allowed) ----------------
__device__ __align__(16) h16 g_ee[NE*D];
__device__ __align__(16) h16 g_ii[NK*D];
__device__ __align__(16) h16 g_ke[NK*D];
__device__ __align__(16) h16 g_ii2[NK*D];
__device__ __align__(16) h16 g_nb[NE*D];
__device__ __align__(16) h16 g_nc[NE*D];
__device__ __align__(16) h16 g_hiI[NE*D];
__device__ __align__(16) h16 g_sc[NE*D];
__device__ __align__(16) h16 g_W[7][128*256];       // per stage [128 n][256 k]
__device__ __align__(16) float g_M1[DD], g_M2[DD], g_M3[DD], g_M4[DD];
__device__ __align__(16) float g_c1[D], g_c2[D];
// CSR (B = belong, C = collab)
__device__ __align__(16) int   g_degB[NE], g_degC[NE];
__device__ __align__(16) int   g_rpB[NE+1], g_rpC[NE+1];
__device__ __align__(16) int   g_curB[NE], g_curC[NE];
__device__ __align__(16) int   g_esrcB[EDG], g_esrcC[EDG];
__device__ __align__(16) float g_ewC[EDG];
__device__ __align__(16) unsigned long long g_pub[2*128];   // packed (sum<<32)|flag

// ---------------- host-side aux (streams/events created once) ----------------
struct Aux {
    cudaStream_t s2, s3, s4;
    cudaEvent_t evF, evJ2, evJ3, evJ4, evAB;
    Aux() {
        cudaStreamCreateWithFlags(&s2, cudaStreamNonBlocking);
        cudaStreamCreateWithFlags(&s3, cudaStreamNonBlocking);
        cudaStreamCreateWithFlags(&s4, cudaStreamNonBlocking);
        cudaEventCreateWithFlags(&evF,  cudaEventDisableTiming);
        cudaEventCreateWithFlags(&evJ2, cudaEventDisableTiming);
        cudaEventCreateWithFlags(&evJ3, cudaEventDisableTiming);
        cudaEventCreateWithFlags(&evJ4, cudaEventDisableTiming);
        cudaEventCreateWithFlags(&evAB, cudaEventDisableTiming);
    }
};
static Aux g_aux;

// ---------------- small helpers ----------------
__device__ __forceinline__ uint32_t s2u(const void* p) {
    uint32_t a;
    asm("{ .reg .u64 t; cvta.to.shared.u64 t, %1; cvt.u32.u64 %0, t; }" : "=r"(a) : "l"(p));
    return a;
}
__device__ __forceinline__ uint32_t packh(h16 a, h16 b) {
    return ((uint32_t)__half_as_ushort(b) << 16) | (uint32_t)__half_as_ushort(a);
}
__device__ __forceinline__ float hlo(uint32_t u) {
    return __half2float(__ushort_as_half((unsigned short)(u & 0xFFFF)));
}
__device__ __forceinline__ float hhi(uint32_t u) {
    return __half2float(__ushort_as_half((unsigned short)(u >> 16)));
}
__device__ __forceinline__ void ldmx4(uint32_t* r, uint32_t addr) {
    asm volatile("ldmatrix.sync.aligned.m8n8.x4.shared.b16 {%0,%1,%2,%3}, [%4];"
                 : "=r"(r[0]), "=r"(r[1]), "=r"(r[2]), "=r"(r[3]) : "r"(addr));
}
__device__ __forceinline__ void mma16816(float* c, const uint32_t* a, uint32_t b0, uint32_t b1) {
    asm volatile("mma.sync.aligned.m16n8k16.row.col.f32.f16.f16.f32 "
                 "{%0,%1,%2,%3}, {%4,%5,%6,%7}, {%8,%9}, {%0,%1,%2,%3};"
                 : "+f"(c[0]), "+f"(c[1]), "+f"(c[2]), "+f"(c[3])
                 : "r"(a[0]), "r"(a[1]), "r"(a[2]), "r"(a[3]), "r"(b0), "r"(b1));
}
__device__ __forceinline__ void cp16(uint32_t s, const void* g) {
    asm volatile("cp.async.cg.shared.global [%0], [%1], 16;" :: "r"(s), "l"(g));
}
// convert 8 fp32 -> 8 fp16 (one uint4 store)
__device__ __forceinline__ void cvt8(const float* __restrict__ src, h16* __restrict__ dst) {
    float4 a = *(const float4*)src;
    float4 b = *(const float4*)(src + 4);
    __half2 h0 = __float22half2_rn(make_float2(a.x, a.y));
    __half2 h1 = __float22half2_rn(make_float2(a.z, a.w));
    __half2 h2 = __float22half2_rn(make_float2(b.x, b.y));
    __half2 h3 = __float22half2_rn(make_float2(b.z, b.w));
    uint4 o;
    o.x = *(uint32_t*)&h0; o.y = *(uint32_t*)&h1;
    o.z = *(uint32_t*)&h2; o.w = *(uint32_t*)&h3;
    *(uint4*)dst = o;
}

// ---------------- SMEM layout ----------------
#define T_ROW    144
#define CH_B     18432
#define CH_BUF   36864
#define TILE_OFF 73728
#define TT_ROW   272
#define SM_TOTAL 108544
#define CF_ROW   528

// ---------------- generic GEMM pass (identical to R14) ----------------
template <int A1S, int A2S, int ACT, int OUT>
__device__ __forceinline__ void gpass(
    char* smem, uint32_t sb, int tid, int lane, int wid, int mbrow, int M,
    const h16* gA1, const h16* gA2, const h16* w, const float* bias,
    h16* go16, float* go32)
{
    int wr = wid & 3, wc = wid >> 2;

    auto load_chunk = [&](int c, int buf) {
        int k0 = (c & 1) * 64;
        bool a_smem = (c < 2) ? (A1S != 0) : (A2S != 0);
        const h16* A = (c < 2) ? gA1 : gA2;
        if (!a_smem) {
#pragma unroll
            for (int u = 0; u < 4; ++u) {
                int i = u * 256 + tid;
                int row = i >> 3, g = i & 7;
                int grow = mbrow + row;
                if (grow < M)
                    cp16(sb + buf * CH_BUF + row * T_ROW + g * 16,
                         A + (size_t)grow * 128 + k0 + g * 8);
            }
        }
#pragma unroll
        for (int u = 0; u < 4; ++u) {
            int i = u * 256 + tid;
            int n = i >> 3, g = i & 7;
            cp16(sb + buf * CH_BUF + CH_B + n * T_ROW + g * 16,
                 w + n * 256 + c * 64 + g * 8);
        }
        asm volatile("cp.async.commit_group;" ::: "memory");
    };

    load_chunk(0, 0);
    load_chunk(1, 1);

    float acc[2][8][4];
#pragma unroll
    for (int mi = 0; mi < 2; ++mi)
#pragma unroll
        for (int ni = 0; ni < 8; ++ni)
#pragma unroll
            for (int q = 0; q < 4; ++q) acc[mi][ni][q] = 0.f;

    int l15 = lane & 15, lkb = (lane >> 4) * 16;

#pragma unroll
    for (int c = 0; c < 4; ++c) {
        if (c < 3) asm volatile("cp.async.wait_group 1;" ::: "memory");
        else       asm volatile("cp.async.wait_group 0;" ::: "memory");
        __syncthreads();

        int buf = c & 1;
        bool a_smem = (c < 2) ? (A1S != 0) : (A2S != 0);
        uint32_t Ab;
        int arow;
        if (a_smem) {
            Ab = sb + TILE_OFF + (uint32_t)(wr * 32 + l15) * TT_ROW + lkb + (c & 1) * 128;
            arow = TT_ROW;
        } else {
            Ab = sb + buf * CH_BUF + (uint32_t)(wr * 32 + l15) * T_ROW + lkb;
            arow = T_ROW;
        }
        uint32_t Bb = sb + buf * CH_BUF + CH_B + (uint32_t)(wc * 64 + l15) * T_ROW + lkb;
#pragma unroll
        for (int s = 0; s < 4; ++s) {
            uint32_t Aks = Ab + s * 32;
            uint32_t Bks = Bb + s * 32;
            uint32_t A0[4], A1[4];
            ldmx4(A0, Aks);
            ldmx4(A1, Aks + 16 * arow);
            uint32_t B[4][4];
#pragma unroll
            for (int nb = 0; nb < 4; ++nb) ldmx4(B[nb], Bks + nb * (16 * T_ROW));
#pragma unroll
            for (int ni = 0; ni < 8; ++ni) {
                int nb = ni >> 1, hb = ni & 1;
                mma16816(acc[0][ni], A0, B[nb][hb], B[nb][2 + hb]);
                mma16816(acc[1][ni], A1, B[nb][hb], B[nb][2 + hb]);
            }
        }
        __syncthreads();
        if (c + 2 < 4) load_chunk(c + 2, buf);
    }

    int quad = lane >> 2, tq = lane & 3;
    if (OUT == 2) {
#pragma unroll
        for (int ni = 0; ni < 8; ++ni) {
            int cbase = wc * 64 + ni * 8 + tq * 2;
            float bv0 = __ldg(bias + cbase), bv1 = __ldg(bias + cbase + 1);
#pragma unroll
            for (int mi = 0; mi < 2; ++mi)
#pragma unroll
                for (int h = 0; h < 2; ++h) {
                    int row = wr * 32 + mi * 16 + quad + h * 8;
                    float x0 = acc[mi][ni][2 * h + 0] + bv0;
                    float x1 = acc[mi][ni][2 * h + 1] + bv1;
                    if (ACT == 1) { x0 = fmaxf(x0, 0.f); x1 = fmaxf(x1, 0.f); }
                    if (ACT == 2) { x0 = (x0 >= 0.f) ? x0 : 0.2f * x0;
                                    x1 = (x1 >= 0.f) ? x1 : 0.2f * x1; }
                    *(float2*)(smem + row * CF_ROW + cbase * 4) = make_float2(x0, x1);
                }
        }
        __syncthreads();
#pragma unroll
        for (int it = 0; it < 16; ++it) {
            int r = wid * 16 + it;
            int grow = mbrow + r;
            if (grow >= M) continue;
            float4 v = *(float4*)(smem + r * CF_ROW + lane * 16);
            *(float4*)(go32 + (size_t)grow * 128 + lane * 4) = v;
        }
    } else {
#pragma unroll
        for (int ni = 0; ni < 8; ++ni) {
            int cbase = wc * 64 + ni * 8 + tq * 2;
            float bv0 = __ldg(bias + cbase), bv1 = __ldg(bias + cbase + 1);
#pragma unroll
            for (int mi = 0; mi < 2; ++mi)
#pragma unroll
                for (int h = 0; h < 2; ++h) {
                    int row = wr * 32 + mi * 16 + quad + h * 8;
                    float x0 = acc[mi][ni][2 * h + 0] + bv0;
                    float x1 = acc[mi][ni][2 * h + 1] + bv1;
                    if (ACT == 1) { x0 = fmaxf(x0, 0.f); x1 = fmaxf(x1, 0.f); }
                    if (ACT == 2) { x0 = (x0 >= 0.f) ? x0 : 0.2f * x0;
                                    x1 = (x1 >= 0.f) ? x1 : 0.2f * x1; }
                    *(uint32_t*)(smem + TILE_OFF + row * TT_ROW + cbase * 2) =
                        packh(__float2half_rn(x0), __float2half_rn(x1));
                }
        }
        __syncthreads();
        if (OUT == 1) {
            int row2 = lane >> 4, colg = lane & 15;
#pragma unroll
            for (int it = 0; it < 8; ++it) {
                int r = wid * 16 + it * 2 + row2;
                int grow = mbrow + r;
                if (grow >= M) continue;
                uint4 v = *(uint4*)(smem + TILE_OFF + r * TT_ROW + colg * 16);
                *(uint4*)(go16 + (size_t)grow * 128 + colg * 8) = v;
            }
        }
    }
}

// ---------------- GEMM kernels ----------------
__global__ void __launch_bounds__(256, 2) gemm1(
    const h16* __restrict__ a1, const h16* __restrict__ a2,
    const h16* __restrict__ w, const float* __restrict__ bias,
    h16* __restrict__ o, int M)
{
    extern __shared__ char smem[];
    uint32_t sb = s2u(smem);
    gpass<0, 0, 0, 1>(smem, sb, threadIdx.x, threadIdx.x & 31, threadIdx.x >> 5,
                      blockIdx.x * 128, M, a1, a2, w, bias, o, nullptr);
}

__global__ void __launch_bounds__(256, 2) fused3_a(
    const h16* __restrict__ ee, const h16* __restrict__ nb,
    const h16* __restrict__ w0, const float* __restrict__ b0,
    const h16* __restrict__ w1, const float* __restrict__ b1,
    const h16* __restrict__ w2, const float* __restrict__ b2,
    h16* __restrict__ hiI, h16* __restrict__ sc, int M)
{
    extern __shared__ char smem[];
    uint32_t sb = s2u(smem);
    int tid = threadIdx.x, lane = tid & 31, wid = tid >> 5, mb = blockIdx.x * 128;
    gpass<0, 0, 1, 0>(smem, sb, tid, lane, wid, mb, M, ee, nb, w0, b0, nullptr, nullptr);
    gpass<1, 0, 0, 1>(smem, sb, tid, lane, wid, mb, M, nullptr, nb, w1, b1, hiI, nullptr);
    gpass<1, 0, 0, 1>(smem, sb, tid, lane, wid, mb, M, nullptr, ee, w2, b2, sc, nullptr);
}

__global__ void __launch_bounds__(256, 2) fused3_b(
    const h16* __restrict__ ee, const h16* __restrict__ nc,
    const h16* __restrict__ w0, const float* __restrict__ b0,
    const h16* __restrict__ w1, const float* __restrict__ b1,
    const h16* __restrict__ hiI, const h16* __restrict__ w2,
    const float* __restrict__ b2, float* __restrict__ out, int M)
{
    extern __shared__ char smem[];
    uint32_t sb = s2u(smem);
    int tid = threadIdx.x, lane = tid & 31, wid = tid >> 5, mb = blockIdx.x * 128;
    gpass<0, 0, 1, 0>(smem, sb, tid, lane, wid, mb, M, ee, nc, w0, b0, nullptr, nullptr);
    gpass<1, 0, 0, 0>(smem, sb, tid, lane, wid, mb, M, nullptr, nc, w1, b1, nullptr, nullptr);
    gpass<0, 1, 2, 2>(smem, sb, tid, lane, wid, mb, M, hiI, nullptr, w2, b2, nullptr, out);
}

// ---------------- weight split helper ----------------
__device__ __forceinline__ void conv_w_one(int stage, int idx, const float* a, const float* b) {
    int n = idx >> 8, k = idx & 255;
    float v = b ? (k < 128 ? a[n * 128 + k] : b[n * 128 + (k - 128)]) : a[idx];
    g_W[stage][idx] = __float2half_rn(v);
}

// ---------------- prep0: vectorized 8 elem/thread (ii, ke, stage0 weights) ----------------
// ii: NK*D = 1.28M elems -> 625 blocks; ke: 625 blocks; w4: 32768 elems -> 16 blocks
__global__ void prep0(const float* __restrict__ ii, const float* __restrict__ k_emb,
                      const float* __restrict__ w4W) {
    int bid = blockIdx.x, tid = threadIdx.x;
    if (bid < 625) {
        int i = (bid * 256 + tid) * 8;
        cvt8(ii + i, g_ii + i);
    } else if (bid < 1250) {
        int i = ((bid - 625) * 256 + tid) * 8;
        cvt8(k_emb + i, g_ke + i);
    } else {
        int i = ((bid - 1250) * 256 + tid) * 8;
        cvt8(w4W + i, (h16*)g_W + i);          // stage 0 at offset 0
    }
}

// ---------------- prepE1: vectorized e_emb + folds + stages 1,3,4,6 weights ----------------
// e_emb: NE*D = 12.8M elems / 8 = 1.6M threads -> 6250 blocks
__global__ void prepE1(const float* __restrict__ e_emb,
                       const float* __restrict__ w2W, const float* __restrict__ w2b,
                       const float* __restrict__ w3W, const float* __restrict__ w3b,
                       const float* __restrict__ ekS1, const float* __restrict__ ekN1,
                       const float* __restrict__ eeS1, const float* __restrict__ eeN1,
                       const float* __restrict__ ekb1, const float* __restrict__ eeb1,
                       const float* __restrict__ ek_self, const float* __restrict__ ek_neigh,
                       const float* __restrict__ w1W, const float* __restrict__ ee_self,
                       const float* __restrict__ ee_neigh, const float* __restrict__ combW) {
    int bid = blockIdx.x, tid = threadIdx.x;
    if (bid < 6250) {
        int i = (bid * 256 + tid) * 8;
        cvt8(e_emb + i, g_ee + i);
    } else if (bid < 6506) {                     // fold_mats: 256 blocks
        int lb = bid - 6250;
        int mat = lb >> 6;
        int idx = (lb & 63) * 256 + tid;
        const float* A = (mat < 2) ? w2W : w3W;
        const float* B = (mat == 0) ? ekS1 : (mat == 1) ? ekN1 : (mat == 2) ? eeS1 : eeN1;
        float* O = (mat == 0) ? g_M1 : (mat == 1) ? g_M2 : (mat == 2) ? g_M3 : g_M4;
        int n = idx >> 7, k = idx & 127;
        float acc = 0.f;
#pragma unroll 8
        for (int j = 0; j < 128; ++j)
            acc += A[n * 128 + j] * B[j * 128 + k];
        O[idx] = acc;
    } else if (bid == 6506) {                    // fold_bias
        int t = tid;
        if (t < 128) {
            float a = 0.f, b = 0.f;
#pragma unroll 8
            for (int j = 0; j < 128; ++j) {
                a += w2W[t * 128 + j] * ekb1[j];
                b += w3W[t * 128 + j] * eeb1[j];
            }
            g_c1[t] = a + w2b[t];
            g_c2[t] = b + w3b[t];
        }
    } else {                                     // stages 1, 3, 4, 6 weight splits: 512 blocks
        int lb = bid - 6507;
        int which = lb >> 7;
        int idx = (lb & 127) * 256 + tid;
        if (which == 0)      conv_w_one(1, idx, ek_self, ek_neigh);
        else if (which == 1) conv_w_one(3, idx, w1W, nullptr);
        else if (which == 2) conv_w_one(4, idx, ee_self, ee_neigh);
        else                 conv_w_one(6, idx, combW, nullptr);
    }
}

__global__ void prepE2() {
    int bid = blockIdx.x;
    int idx = (bid & 127) * 256 + threadIdx.x;
    if (bid < 128) conv_w_one(2, idx, g_M1, g_M2);
    else           conv_w_one(5, idx, g_M3, g_M4);
}

// ---------------- CSR build (R14 versions) ----------------
__global__ void zero_k(int* __restrict__ deg, unsigned long long* __restrict__ pub) {
    int i = blockIdx.x * blockDim.x + threadIdx.x;
    if (i < NE) deg[i] = 0;
    if (blockIdx.x == 0 && threadIdx.x < 128) pub[threadIdx.x] = 0ull;
}
__global__ void count_k(const int* __restrict__ dst, int* __restrict__ deg, int E) {
    int i = blockIdx.x * blockDim.x + threadIdx.x;
    if (i < E) atomicAdd(&deg[dst[i]], 1);
}
__global__ void scan_lb(const int* __restrict__ deg, int* __restrict__ rp,
                        int* __restrict__ cur, unsigned long long* __restrict__ pub,
                        int nblk) {
    __shared__ int ws[32];
    __shared__ int s_pref;
    int bid = blockIdx.x, tid = threadIdx.x, lane = tid & 31, wid = tid >> 5;
    int i = bid * 1024 + tid;
    int v = (i < NE) ? deg[i] : 0;
    int inc = v;
#pragma unroll
    for (int o = 1; o < 32; o <<= 1) {
        int x = __shfl_up_sync(0xFFFFFFFFu, inc, o);
        if (lane >= o) inc += x;
    }
    if (lane == 31) ws[wid] = inc;
    __syncthreads();
    if (wid == 0) {
        int s = ws[lane];
#pragma unroll
        for (int o = 1; o < 32; o <<= 1) {
            int x = __shfl_up_sync(0xFFFFFFFFu, s, o);
            if (lane >= o) s += x;
        }
        ws[lane] = s;
    }
    __syncthreads();
    int off = wid ? ws[wid - 1] : 0;
    int total = ws[31];
    __syncthreads();
    if (tid == 0)
        atomicExch(&pub[bid], ((unsigned long long)(unsigned)total << 32) | 1ull);
    int contrib = 0;
    if (tid < bid) {
        unsigned long long x;
        do { x = atomicAdd(&pub[tid], 0ull); } while (!(x & 1ull));
        contrib = (int)(x >> 32);
    }
#pragma unroll
    for (int o = 16; o > 0; o >>= 1)
        contrib += __shfl_xor_sync(0xFFFFFFFFu, contrib, o);
    if (lane == 0) ws[wid] = contrib;
    __syncthreads();
    if (tid == 0) {
        int s = 0;
        for (int w = 0; w < 32; ++w) s += ws[w];
        s_pref = s;
    }
    __syncthreads();
    int base = s_pref;
    if (i < NE) {
        int val = base + off + inc - v;
        rp[i] = val;
        cur[i] = val;
    }
    if (bid == nblk - 1 && tid == 0) rp[NE] = base + total;
}
template <int WEIGHTED>
__global__ void scatter_k(const int* __restrict__ src, const int* __restrict__ dst,
                          const float* __restrict__ ewin, int* __restrict__ cur,
                          int* __restrict__ esrc, float* __restrict__ ewout, int E) {
    int i = blockIdx.x * blockDim.x + threadIdx.x;
    if (i >= E) return;
    int pos = atomicAdd(&cur[dst[i]], 1);
    esrc[pos] = src[i];
    if (WEIGHTED) ewout[pos] = ewin[i];
}

// ---------------- mean aggregation: warp per dst node, 2 edges/iter, uint4 loads ----------------
template <int WEIGHTED>
__global__ void aggregate_kernel(const h16* __restrict__ sh, h16* __restrict__ oh,
                                 const int* __restrict__ rowptr, const int* __restrict__ esrc,
                                 const float* __restrict__ ew, int n) {
    int gw = (blockIdx.x * blockDim.x + threadIdx.x) >> 5;
    int lane = threadIdx.x & 31;
    if (gw >= n) return;
    int s0 = rowptr[gw], s1 = rowptr[gw + 1];
    int half = lane >> 4, l16 = lane & 15;
    float a[8];
#pragma unroll
    for (int d = 0; d < 8; ++d) a[d] = 0.f;
    int j = s0;
    for (; j + 1 < s1; j += 2) {
        int e = j + half;
        int sidx = esrc[e];
        uint4 u = *(const uint4*)(sh + (size_t)sidx * D + l16 * 8);
        float w = WEIGHTED ? ew[e] : 1.0f;
        a[0] += hlo(u.x) * w; a[1] += hhi(u.x) * w;
        a[2] += hlo(u.y) * w; a[3] += hhi(u.y) * w;
        a[4] += hlo(u.z) * w; a[5] += hhi(u.z) * w;
        a[6] += hlo(u.w) * w; a[7] += hhi(u.w) * w;
    }
    if (j < s1 && half == 0) {
        int sidx = esrc[j];
        uint4 u = *(const uint4*)(sh + (size_t)sidx * D + l16 * 8);
        float w = WEIGHTED ? ew[j] : 1.0f;
        a[0] += hlo(u.x) * w; a[1] += hhi(u.x) * w;
        a[2] += hlo(u.y) * w; a[3] += hhi(u.y) * w;
        a[4] += hlo(u.z) * w; a[5] += hhi(u.z) * w;
        a[6] += hlo(u.w) * w; a[7] += hhi(u.w) * w;
    }
#pragma unroll
    for (int d = 0; d < 8; ++d) a[d] += __shfl_xor_sync(0xFFFFFFFFu, a[d], 16);
    if (half == 0) {
        float inv = 1.0f / fmaxf((float)(s1 - s0), 1.0f);
        uint4 o;
        o.x = packh(__float2half_rn(a[0] * inv), __float2half_rn(a[1] * inv));
        o.y = packh(__float2half_rn(a[2] * inv), __float2half_rn(a[3] * inv));
        o.z = packh(__float2half_rn(a[4] * inv), __float2half_rn(a[5] * inv));
        o.w = packh(__float2half_rn(a[6] * inv), __float2half_rn(a[7] * inv));
        *(uint4*)(oh + (size_t)gw * D + l16 * 8) = o;
    }
}

// ---------------- launch ----------------
extern "C" void kernel_launch(void* const* d_in, const int* in_sizes, int n_in,
                              void* d_out, int out_size) {
    const float* ii      = (const float*)d_in[0];
    const float* e_emb   = (const float*)d_in[1];
    const float* k_emb   = (const float*)d_in[2];
    const float* cf_ew   = (const float*)d_in[3];
    const int*   b_src   = (const int*)d_in[4];
    const int*   b_dst   = (const int*)d_in[5];
    const int*   c_src   = (const int*)d_in[6];
    const int*   c_dst   = (const int*)d_in[7];
    const float* ek_self = (const float*)d_in[8];
    const float* ek_neigh= (const float*)d_in[9];
    const float* ek_bias = (const float*)d_in[10];
    const float* ee_self = (const float*)d_in[11];
    const float* ee_neigh= (const float*)d_in[12];
    const float* ee_bias = (const float*)d_in[13];
    const float* w1W = (const float*)d_in[14];
    const float* w1b = (const float*)d_in[15];
    const float* w2W = (const float*)d_in[16];
    const float* w2b = (const float*)d_in[17];
    const float* w3W = (const float*)d_in[18];
    const float* w3b = (const float*)d_in[19];
    const float* w4W = (const float*)d_in[20];
    const float* w4b = (const float*)d_in[21];
    const float* combW = (const float*)d_in[22];
    const float* combb = (const float*)d_in[23];
    float* out = (float*)d_out;

    int n_k = in_sizes[0] / D;
    int n_e = in_sizes[1] / D;
    int E   = in_sizes[4];

    h16 *ee, *iip, *ke, *ii2, *nb, *nc, *hiI, *sc, *W;
    float *p_c1, *p_c2, *p_ewC;
    int *p_rpB, *p_rpC, *p_esB, *p_esC, *p_degB, *p_degC, *p_curB, *p_curC;
    unsigned long long* p_pub;
    cudaGetSymbolAddress((void**)&ee,  g_ee);
    cudaGetSymbolAddress((void**)&iip, g_ii);
    cudaGetSymbolAddress((void**)&ke,  g_ke);
    cudaGetSymbolAddress((void**)&ii2, g_ii2);
    cudaGetSymbolAddress((void**)&nb,  g_nb);
    cudaGetSymbolAddress((void**)&nc,  g_nc);
    cudaGetSymbolAddress((void**)&hiI, g_hiI);
    cudaGetSymbolAddress((void**)&sc,  g_sc);
    cudaGetSymbolAddress((void**)&W,   g_W);
    cudaGetSymbolAddress((void**)&p_c1, g_c1);   cudaGetSymbolAddress((void**)&p_c2, g_c2);
    cudaGetSymbolAddress((void**)&p_rpB, g_rpB); cudaGetSymbolAddress((void**)&p_rpC, g_rpC);
    cudaGetSymbolAddress((void**)&p_esB, g_esrcB); cudaGetSymbolAddress((void**)&p_esC, g_esrcC);
    cudaGetSymbolAddress((void**)&p_ewC, g_ewC);
    cudaGetSymbolAddress((void**)&p_degB, g_degB); cudaGetSymbolAddress((void**)&p_degC, g_degC);
    cudaGetSymbolAddress((void**)&p_curB, g_curB); cudaGetSymbolAddress((void**)&p_curC, g_curC);
    cudaGetSymbolAddress((void**)&p_pub, g_pub);

    cudaFuncSetAttribute(gemm1,    cudaFuncAttributeMaxDynamicSharedMemorySize, SM_TOTAL);
    cudaFuncSetAttribute(fused3_a, cudaFuncAttributeMaxDynamicSharedMemorySize, SM_TOTAL);
    cudaFuncSetAttribute(fused3_b, cudaFuncAttributeMaxDynamicSharedMemorySize, SM_TOTAL);

    int gE   = (E + 255) / 256;
    int gNe  = (n_e + 255) / 256;
    int gSc  = (n_e + 1023) / 1024;              // 98 blocks (<= 148 SMs, lookback-safe)
    int gAgg = (n_e * 32 + 255) / 256;
    int gbK  = (n_k + 127) / 128;
    int gbE  = (n_e + 127) / 128;

    // ---- fork ----
    cudaEventRecord(g_aux.evF, 0);
    cudaStreamWaitEvent(g_aux.s2, g_aux.evF, 0);
    cudaStreamWaitEvent(g_aux.s4, g_aux.evF, 0);

    // s2: belong CSR ONLY (gets the head to itself — no CSR-C contention)
    zero_k<<<gNe, 256, 0, g_aux.s2>>>(p_degB, p_pub);
    count_k<<<gE, 256, 0, g_aux.s2>>>(b_dst, p_degB, E);
    scan_lb<<<gSc, 1024, 0, g_aux.s2>>>(p_degB, p_rpB, p_curB, p_pub, gSc);
    scatter_k<0><<<gE, 256, 0, g_aux.s2>>>(b_src, b_dst, nullptr, p_curB, p_esB, nullptr, E);
    cudaEventRecord(g_aux.evJ2, g_aux.s2);

    // s4: heavy prep (vectorized e_emb conversion)
    prepE1<<<7019, 256, 0, g_aux.s4>>>(e_emb, w2W, w2b, w3W, w3b,
                                       ek_self + DD, ek_neigh + DD, ee_self + DD, ee_neigh + DD,
                                       ek_bias + D, ee_bias + D,
                                       ek_self, ek_neigh, w1W, ee_self, ee_neigh, combW);
    prepE2<<<256, 256, 0, g_aux.s4>>>();
    cudaEventRecord(g_aux.evJ4, g_aux.s4);

    // main: minimal prep (vectorized) + stage0 GEMM
    prep0<<<1266, 256>>>(ii, k_emb, w4W);
    gemm1<<<gbK, 256, SM_TOTAL>>>(iip, ke, W + 0*32768, w4b, ii2, n_k);

    // join belong CSR → aggB (record event so CSR-C can start right after)
    cudaStreamWaitEvent(0, g_aux.evJ2, 0);
    aggregate_kernel<0><<<gAgg, 256>>>(ii2, nb, p_rpB, p_esB, nullptr, n_e);
    cudaEventRecord(g_aux.evAB, 0);

    // s3: collab CSR — runs concurrently with F1 (compute-bound window)
    cudaStreamWaitEvent(g_aux.s3, g_aux.evAB, 0);
    zero_k<<<gNe, 256, 0, g_aux.s3>>>(p_degC, p_pub + 128);
    count_k<<<gE, 256, 0, g_aux.s3>>>(c_dst, p_degC, E);
    scan_lb<<<gSc, 1024, 0, g_aux.s3>>>(p_degC, p_rpC, p_curC, p_pub + 128, gSc);
    scatter_k<1><<<gE, 256, 0, g_aux.s3>>>(c_src, c_dst, cf_ew, p_curC, p_esC, p_ewC, E);
    cudaEventRecord(g_aux.evJ3, g_aux.s3);

    // main: F1 (overlaps CSR-C)
    cudaStreamWaitEvent(0, g_aux.evJ4, 0);
    fused3_a<<<gbE, 256, SM_TOTAL>>>(ee, nb, W + 1*32768, ek_bias,
                                     W + 2*32768, p_c1, W + 3*32768, w1b,
                                     hiI, sc, n_e);

    // join collab CSR → aggC → F2
    cudaStreamWaitEvent(0, g_aux.evJ3, 0);
    aggregate_kernel<1><<<gAgg, 256>>>(sc, nc, p_rpC, p_esC, p_ewC, n_e);
    fused3_b<<<gbE, 256, SM_TOTAL>>>(ee, nc, W + 4*32768, ee_bias,
                                     W + 5*32768, p_c2, hiI, W + 6*32768,
                                     combb, out, n_e);
}